// round 2
// baseline (speedup 1.0000x reference)
#include <cuda_runtime.h>

#define D      128
#define NMAX   50000
#define EMAX   600000

// Scratch (device globals: allocation-free per harness rules)
__device__ float g_h[NMAX * D];      // h_scaled = (x @ W) * dinv[row]
__device__ float g_x[NMAX * D];      // layer output ping buffer
__device__ float g_dinv[NMAX];
__device__ int   g_cnt[NMAX];
__device__ int   g_off[NMAX + 1];
__device__ int   g_cur[NMAX];
__device__ int   g_col[EMAX];        // CSR (by dst) column = src ids
__device__ int   g_is64;             // edge_index dtype flag (1 = int64)

// ---------------------------------------------------------------- dtype probe
// If edge_index is int64 with values in [0, 50000), every odd 32-bit word is 0.
__global__ void detect_kernel(const int* __restrict__ w) {
    int is64 = 1;
    #pragma unroll 1
    for (int i = 1; i < 512; i += 2)
        if (w[i] != 0) { is64 = 0; break; }
    g_is64 = is64;
}

__device__ __forceinline__ int load_idx(const void* buf, int i) {
    if (g_is64) return (int)((const long long*)buf)[i];
    return ((const int*)buf)[i];
}

// ---------------------------------------------------------------- CSR build
__global__ void zero_cnt_kernel(int N) {
    int i = blockIdx.x * blockDim.x + threadIdx.x;
    if (i < N) g_cnt[i] = 0;
}

__global__ void count_kernel(const void* __restrict__ ei, int E) {
    int e = blockIdx.x * blockDim.x + threadIdx.x;
    if (e < E) {
        int dst = load_idx(ei, E + e);
        atomicAdd(&g_cnt[dst], 1);
    }
}

__global__ void dinv_kernel(int N) {
    int i = blockIdx.x * blockDim.x + threadIdx.x;
    if (i < N) g_dinv[i] = rsqrtf((float)(g_cnt[i] + 1));  // +1 self-loop
}

__global__ void scan_kernel(int N) {
    __shared__ int partial[1024];
    int t = threadIdx.x;
    int per = (N + 1023) / 1024;
    int beg = t * per;
    int end = beg + per; if (end > N) end = N;
    int s = 0;
    for (int i = beg; i < end; i++) s += g_cnt[i];
    partial[t] = s;
    __syncthreads();
    // Hillis-Steele inclusive scan
    for (int ofs = 1; ofs < 1024; ofs <<= 1) {
        int v = (t >= ofs) ? partial[t - ofs] : 0;
        __syncthreads();
        partial[t] += v;
        __syncthreads();
    }
    int base = (t == 0) ? 0 : partial[t - 1];
    for (int i = beg; i < end; i++) {
        g_off[i] = base;
        g_cur[i] = base;
        base += g_cnt[i];
    }
    if (t == 1023) g_off[N] = partial[1023];
}

__global__ void fill_kernel(const void* __restrict__ ei, int E) {
    int e = blockIdx.x * blockDim.x + threadIdx.x;
    if (e < E) {
        int dst = load_idx(ei, E + e);
        int src = load_idx(ei, e);
        int p = atomicAdd(&g_cur[dst], 1);
        g_col[p] = src;
    }
}

// ---------------------------------------------------------------- GEMM
// H[m][n] = dinv[m] * sum_k relu?(X[m][k]) * W[k][n]
// Tile: 64 rows x 128 cols (full N), K chunked by 32. 256 threads, 4x8 per thread.
__global__ void __launch_bounds__(256) gemm_kernel(
    const float* __restrict__ X, const float* __restrict__ Wm,
    float* __restrict__ H, int N, int apply_relu)
{
    __shared__ float As[64 * 32];
    __shared__ float Bs[32 * 128];
    int tid = threadIdx.x;
    int tx = tid & 15;          // 0..15 -> 8 cols each
    int ty = tid >> 4;          // 0..15 -> 4 rows each
    int m0 = blockIdx.x * 64;

    float acc[4][8];
    #pragma unroll
    for (int i = 0; i < 4; i++)
        #pragma unroll
        for (int j = 0; j < 8; j++) acc[i][j] = 0.f;

    for (int kc = 0; kc < D; kc += 32) {
        // load A tile 64x32 (2 float4 per thread)
        #pragma unroll
        for (int r = 0; r < 2; r++) {
            int idx = tid + r * 256;       // 0..511 float4 slots
            int row = idx >> 3;            // 8 float4 per row
            int c4  = idx & 7;
            int gm  = m0 + row;
            float4 v = make_float4(0.f, 0.f, 0.f, 0.f);
            if (gm < N)
                v = *(const float4*)(X + (size_t)gm * D + kc + c4 * 4);
            if (apply_relu) {
                v.x = fmaxf(v.x, 0.f); v.y = fmaxf(v.y, 0.f);
                v.z = fmaxf(v.z, 0.f); v.w = fmaxf(v.w, 0.f);
            }
            *(float4*)(As + row * 32 + c4 * 4) = v;
        }
        // load B tile 32x128 (4 float4 per thread)
        #pragma unroll
        for (int r = 0; r < 4; r++) {
            int idx = tid + r * 256;       // 0..1023 float4 slots
            int row = idx >> 5;            // 32 float4 per row
            int c4  = idx & 31;
            *(float4*)(Bs + row * D + c4 * 4) =
                *(const float4*)(Wm + (size_t)(kc + row) * D + c4 * 4);
        }
        __syncthreads();

        #pragma unroll
        for (int kk = 0; kk < 32; kk++) {
            float a[4], b[8];
            #pragma unroll
            for (int i = 0; i < 4; i++) a[i] = As[(ty * 4 + i) * 32 + kk];
            #pragma unroll
            for (int j = 0; j < 8; j++) b[j] = Bs[kk * D + tx * 8 + j];
            #pragma unroll
            for (int i = 0; i < 4; i++)
                #pragma unroll
                for (int j = 0; j < 8; j++)
                    acc[i][j] = fmaf(a[i], b[j], acc[i][j]);
        }
        __syncthreads();
    }

    #pragma unroll
    for (int i = 0; i < 4; i++) {
        int gm = m0 + ty * 4 + i;
        if (gm < N) {
            float dv = g_dinv[gm];
            float4 o0, o1;
            o0.x = acc[i][0] * dv; o0.y = acc[i][1] * dv;
            o0.z = acc[i][2] * dv; o0.w = acc[i][3] * dv;
            o1.x = acc[i][4] * dv; o1.y = acc[i][5] * dv;
            o1.z = acc[i][6] * dv; o1.w = acc[i][7] * dv;
            *(float4*)(H + (size_t)gm * D + tx * 8)     = o0;
            *(float4*)(H + (size_t)gm * D + tx * 8 + 4) = o1;
        }
    }
}

// ---------------------------------------------------------------- Aggregate
// out[i] = dinv[i] * (h_s[i] + sum_{e in row i} h_s[col[e]]) + b
// one warp per node, lane handles float4 (4 contiguous floats).
__global__ void __launch_bounds__(256) agg_kernel(
    const float* __restrict__ bias, float* __restrict__ out, int N)
{
    int w    = (int)((blockIdx.x * blockDim.x + threadIdx.x) >> 5);
    int lane = threadIdx.x & 31;
    if (w >= N) return;

    const float4* H4 = (const float4*)g_h;
    float4 acc = H4[(size_t)w * 32 + lane];   // self-loop term: h_s[i]
    int beg = g_off[w], end = g_off[w + 1];

    int e = beg;
    // unroll by 2 for a bit of MLP
    for (; e + 1 < end; e += 2) {
        int s0 = g_col[e], s1 = g_col[e + 1];
        float4 v0 = H4[(size_t)s0 * 32 + lane];
        float4 v1 = H4[(size_t)s1 * 32 + lane];
        acc.x += v0.x + v1.x; acc.y += v0.y + v1.y;
        acc.z += v0.z + v1.z; acc.w += v0.w + v1.w;
    }
    if (e < end) {
        int s0 = g_col[e];
        float4 v0 = H4[(size_t)s0 * 32 + lane];
        acc.x += v0.x; acc.y += v0.y; acc.z += v0.z; acc.w += v0.w;
    }

    float dv = g_dinv[w];
    float4 bb = ((const float4*)bias)[lane];
    float4 o;
    o.x = fmaf(acc.x, dv, bb.x);
    o.y = fmaf(acc.y, dv, bb.y);
    o.z = fmaf(acc.z, dv, bb.z);
    o.w = fmaf(acc.w, dv, bb.w);
    ((float4*)out)[(size_t)w * 32 + lane] = o;
}

__global__ void zero_row0_kernel(float* __restrict__ out) {
    int t = threadIdx.x;
    if (t < D) out[t] = 0.f;
}

// ---------------------------------------------------------------- launch
extern "C" void kernel_launch(void* const* d_in, const int* in_sizes, int n_in,
                              void* d_out, int out_size)
{
    const float* emb = (const float*)d_in[0];
    const float* W1  = (const float*)d_in[1];
    const float* b1  = (const float*)d_in[2];
    const float* W2  = (const float*)d_in[3];
    const float* b2  = (const float*)d_in[4];
    const float* W3  = (const float*)d_in[5];
    const float* b3  = (const float*)d_in[6];
    const void*  ei  = d_in[7];

    int N = in_sizes[0] / D;
    int E = in_sizes[7] / 2;
    float* out = (float*)d_out;

    void* p;
    cudaGetSymbolAddress(&p, g_h);  float* H = (float*)p;
    cudaGetSymbolAddress(&p, g_x);  float* X = (float*)p;

    int tb = 256;
    // CSR build (per call — deterministic work, cheap)
    detect_kernel<<<1, 1>>>((const int*)ei);
    zero_cnt_kernel<<<(N + tb - 1) / tb, tb>>>(N);
    count_kernel<<<(E + tb - 1) / tb, tb>>>(ei, E);
    dinv_kernel<<<(N + tb - 1) / tb, tb>>>(N);
    scan_kernel<<<1, 1024>>>(N);
    fill_kernel<<<(E + tb - 1) / tb, tb>>>(ei, E);

    int gemm_grid = (N + 63) / 64;
    int agg_grid  = (N + 7) / 8;     // 8 warps/block, 1 warp/node

    // layer 1
    gemm_kernel<<<gemm_grid, 256>>>(emb, W1, H, N, 0);
    agg_kernel<<<agg_grid, 256>>>(b1, X, N);
    // layer 2 (relu fused into A-load)
    gemm_kernel<<<gemm_grid, 256>>>(X, W2, H, N, 1);
    agg_kernel<<<agg_grid, 256>>>(b2, X, N);
    // layer 3
    gemm_kernel<<<gemm_grid, 256>>>(X, W3, H, N, 1);
    agg_kernel<<<agg_grid, 256>>>(b3, out, N);

    zero_row0_kernel<<<1, 128>>>(out);
}

// round 3
// speedup vs baseline: 1.6240x; 1.6240x over previous
#include <cuda_runtime.h>
#include <cuda_bf16.h>

#define D      128
#define NMAX   50000
#define EMAX   600000

// Scratch (device globals: allocation-free per harness rules)
__device__ float g_h[NMAX * D];      // h_scaled = (x @ W) * dinv[row]
__device__ float g_x[NMAX * D];      // layer output ping buffer
__device__ float g_dinv[NMAX];
__device__ int   g_cnt[NMAX];
__device__ int   g_off[NMAX + 1];
__device__ int   g_cur[NMAX];
__device__ int   g_col[EMAX];        // CSR (by dst) column = src ids
__device__ int   g_is64;             // edge_index dtype flag (1 = int64)
__device__ __nv_bfloat16 g_Wh[D * D];   // W^T split hi  [n][k]
__device__ __nv_bfloat16 g_Wl[D * D];   // W^T split lo  [n][k]

// ---------------------------------------------------------------- dtype probe
__global__ void detect_kernel(const int* __restrict__ w) {
    int is64 = 1;
    #pragma unroll 1
    for (int i = 1; i < 512; i += 2)
        if (w[i] != 0) { is64 = 0; break; }
    g_is64 = is64;
}

__device__ __forceinline__ int load_idx(const void* buf, int i) {
    if (g_is64) return (int)((const long long*)buf)[i];
    return ((const int*)buf)[i];
}

// ---------------------------------------------------------------- CSR build
__global__ void zero_cnt_kernel(int N) {
    int i = blockIdx.x * blockDim.x + threadIdx.x;
    if (i < N) g_cnt[i] = 0;
}

__global__ void count_kernel(const void* __restrict__ ei, int E) {
    int e = blockIdx.x * blockDim.x + threadIdx.x;
    if (e < E) atomicAdd(&g_cnt[load_idx(ei, E + e)], 1);
}

__global__ void dinv_kernel(int N) {
    int i = blockIdx.x * blockDim.x + threadIdx.x;
    if (i < N) g_dinv[i] = rsqrtf((float)(g_cnt[i] + 1));  // +1 self-loop
}

__global__ void scan_kernel(int N) {
    __shared__ int partial[1024];
    int t = threadIdx.x;
    int per = (N + 1023) / 1024;
    int beg = t * per;
    int end = beg + per; if (end > N) end = N;
    int s = 0;
    for (int i = beg; i < end; i++) s += g_cnt[i];
    partial[t] = s;
    __syncthreads();
    for (int ofs = 1; ofs < 1024; ofs <<= 1) {
        int v = (t >= ofs) ? partial[t - ofs] : 0;
        __syncthreads();
        partial[t] += v;
        __syncthreads();
    }
    int base = (t == 0) ? 0 : partial[t - 1];
    for (int i = beg; i < end; i++) {
        g_off[i] = base;
        g_cur[i] = base;
        base += g_cnt[i];
    }
    if (t == 1023) g_off[N] = partial[1023];
}

__global__ void fill_kernel(const void* __restrict__ ei, int E) {
    int e = blockIdx.x * blockDim.x + threadIdx.x;
    if (e < E) {
        int dst = load_idx(ei, E + e);
        int src = load_idx(ei, e);
        int p = atomicAdd(&g_cur[dst], 1);
        g_col[p] = src;
    }
}

// ---------------------------------------------------------------- W split
// W [k][n] fp32 -> W^T [n][k] split into bf16 hi + lo.
__global__ void wsplit_kernel(const float* __restrict__ W) {
    int idx = blockIdx.x * blockDim.x + threadIdx.x;   // 16384 threads
    if (idx >= D * D) return;
    int k = idx >> 7, n = idx & 127;
    float v = W[idx];
    __nv_bfloat16 hi = __float2bfloat16(v);
    __nv_bfloat16 lo = __float2bfloat16(v - __bfloat162float(hi));
    g_Wh[n * D + k] = hi;
    g_Wl[n * D + k] = lo;
}

// ---------------------------------------------------------------- Tensor GEMM
// H[m][n] = dinv[m] * sum_k relu?(X[m][k]) * W[k][n]
// Block tile 64(M) x 128(N), full K=128 in smem. 256 thr = 8 warps:
// warp (wm = wid&1) covers 32 rows, (wn = wid>>1) covers 32 cols.
// bf16 split: acc = Ah*Wh + Al*Wh + Ah*Wl   (fp32 accumulate)
#define APAD   8
#define AROW   (D + APAD)                 // 136 bf16 per padded row
#define SM_AH  0
#define SM_AL  (64 * AROW * 2)
#define SM_WH  (2 * 64 * AROW * 2)
#define SM_WL  (SM_WH + D * AROW * 2)
#define SM_TOT (SM_WL + D * AROW * 2)     // 104448 bytes

__device__ __forceinline__ void mma_bf16(
    float& c0, float& c1, float& c2, float& c3,
    unsigned a0, unsigned a1, unsigned a2, unsigned a3,
    unsigned b0, unsigned b1)
{
    asm volatile(
        "mma.sync.aligned.m16n8k16.row.col.f32.bf16.bf16.f32 "
        "{%0,%1,%2,%3}, {%4,%5,%6,%7}, {%8,%9}, {%0,%1,%2,%3};\n"
        : "+f"(c0), "+f"(c1), "+f"(c2), "+f"(c3)
        : "r"(a0), "r"(a1), "r"(a2), "r"(a3), "r"(b0), "r"(b1));
}

__global__ void __launch_bounds__(256) gemm_tc_kernel(
    const float* __restrict__ X, float* __restrict__ H, int N, int apply_relu)
{
    extern __shared__ char smem[];
    __nv_bfloat16* As_h = (__nv_bfloat16*)(smem + SM_AH);
    __nv_bfloat16* As_l = (__nv_bfloat16*)(smem + SM_AL);
    __nv_bfloat16* Ws_h = (__nv_bfloat16*)(smem + SM_WH);
    __nv_bfloat16* Ws_l = (__nv_bfloat16*)(smem + SM_WL);

    int tid = threadIdx.x;
    int m0  = blockIdx.x * 64;

    // ---- load W^T hi/lo (pre-split global) into padded smem: 128 rows x 256B
    {
        const uint4* gh = (const uint4*)g_Wh;
        const uint4* gl = (const uint4*)g_Wl;
        #pragma unroll
        for (int r = 0; r < 8; r++) {
            int idx = tid + r * 256;        // 2048 uint4 chunks
            int row = idx >> 4, ch = idx & 15;
            ((uint4*)((char*)Ws_h + row * AROW * 2))[ch] = gh[row * 16 + ch];
            ((uint4*)((char*)Ws_l + row * AROW * 2))[ch] = gl[row * 16 + ch];
        }
    }

    // ---- load A tile (64x128 fp32), relu, split -> bf16 hi/lo padded smem
    {
        #pragma unroll
        for (int r = 0; r < 8; r++) {
            int idx = tid + r * 256;        // 2048 float4 slots
            int row = idx >> 5, c4 = idx & 31;
            int gm = m0 + row;
            float4 v = make_float4(0.f, 0.f, 0.f, 0.f);
            if (gm < N) v = *(const float4*)(X + (size_t)gm * D + c4 * 4);
            if (apply_relu) {
                v.x = fmaxf(v.x, 0.f); v.y = fmaxf(v.y, 0.f);
                v.z = fmaxf(v.z, 0.f); v.w = fmaxf(v.w, 0.f);
            }
            __nv_bfloat16 h0 = __float2bfloat16(v.x);
            __nv_bfloat16 h1 = __float2bfloat16(v.y);
            __nv_bfloat16 h2 = __float2bfloat16(v.z);
            __nv_bfloat16 h3 = __float2bfloat16(v.w);
            __nv_bfloat16 l0 = __float2bfloat16(v.x - __bfloat162float(h0));
            __nv_bfloat16 l1 = __float2bfloat16(v.y - __bfloat162float(h1));
            __nv_bfloat16 l2 = __float2bfloat16(v.z - __bfloat162float(h2));
            __nv_bfloat16 l3 = __float2bfloat16(v.w - __bfloat162float(h3));
            __nv_bfloat162* ph = (__nv_bfloat162*)(As_h + row * AROW + c4 * 4);
            __nv_bfloat162* pl = (__nv_bfloat162*)(As_l + row * AROW + c4 * 4);
            ph[0] = __nv_bfloat162(h0, h1); ph[1] = __nv_bfloat162(h2, h3);
            pl[0] = __nv_bfloat162(l0, l1); pl[1] = __nv_bfloat162(l2, l3);
        }
    }
    __syncthreads();

    int wid  = tid >> 5, lane = tid & 31;
    int wm   = wid & 1, wn = wid >> 1;
    int g    = lane >> 2;
    int kk   = (lane & 3) * 2;

    float acc[2][4][4];
    #pragma unroll
    for (int mt = 0; mt < 2; mt++)
        #pragma unroll
        for (int nt = 0; nt < 4; nt++)
            #pragma unroll
            for (int r = 0; r < 4; r++) acc[mt][nt][r] = 0.f;

    #pragma unroll
    for (int ks = 0; ks < 8; ks++) {
        int k0 = ks * 16;
        unsigned ah[2][4], al[2][4];
        #pragma unroll
        for (int mt = 0; mt < 2; mt++) {
            int r0 = wm * 32 + mt * 16 + g;
            ah[mt][0] = *(const unsigned*)(As_h + r0 * AROW + k0 + kk);
            ah[mt][1] = *(const unsigned*)(As_h + (r0 + 8) * AROW + k0 + kk);
            ah[mt][2] = *(const unsigned*)(As_h + r0 * AROW + k0 + kk + 8);
            ah[mt][3] = *(const unsigned*)(As_h + (r0 + 8) * AROW + k0 + kk + 8);
            al[mt][0] = *(const unsigned*)(As_l + r0 * AROW + k0 + kk);
            al[mt][1] = *(const unsigned*)(As_l + (r0 + 8) * AROW + k0 + kk);
            al[mt][2] = *(const unsigned*)(As_l + r0 * AROW + k0 + kk + 8);
            al[mt][3] = *(const unsigned*)(As_l + (r0 + 8) * AROW + k0 + kk + 8);
        }
        #pragma unroll
        for (int nt = 0; nt < 4; nt++) {
            int c = wn * 32 + nt * 8 + g;
            unsigned bh0 = *(const unsigned*)(Ws_h + c * AROW + k0 + kk);
            unsigned bh1 = *(const unsigned*)(Ws_h + c * AROW + k0 + kk + 8);
            unsigned bl0 = *(const unsigned*)(Ws_l + c * AROW + k0 + kk);
            unsigned bl1 = *(const unsigned*)(Ws_l + c * AROW + k0 + kk + 8);
            #pragma unroll
            for (int mt = 0; mt < 2; mt++) {
                float* a = acc[mt][nt];
                mma_bf16(a[0], a[1], a[2], a[3],
                         ah[mt][0], ah[mt][1], ah[mt][2], ah[mt][3], bh0, bh1);
                mma_bf16(a[0], a[1], a[2], a[3],
                         al[mt][0], al[mt][1], al[mt][2], al[mt][3], bh0, bh1);
                mma_bf16(a[0], a[1], a[2], a[3],
                         ah[mt][0], ah[mt][1], ah[mt][2], ah[mt][3], bl0, bl1);
            }
        }
    }

    // ---- epilogue: scale by dinv[row], store
    #pragma unroll
    for (int mt = 0; mt < 2; mt++) {
        int r0 = m0 + wm * 32 + mt * 16 + g;
        int r1 = r0 + 8;
        float dv0 = (r0 < N) ? g_dinv[r0] : 0.f;
        float dv1 = (r1 < N) ? g_dinv[r1] : 0.f;
        #pragma unroll
        for (int nt = 0; nt < 4; nt++) {
            int col = wn * 32 + nt * 8 + (lane & 3) * 2;
            float* a = acc[mt][nt];
            if (r0 < N)
                *(float2*)(H + (size_t)r0 * D + col) =
                    make_float2(a[0] * dv0, a[1] * dv0);
            if (r1 < N)
                *(float2*)(H + (size_t)r1 * D + col) =
                    make_float2(a[2] * dv1, a[3] * dv1);
        }
    }
}

// ---------------------------------------------------------------- Aggregate
// out[i] = dinv[i] * (h_s[i] + sum_{e in row i} h_s[col[e]]) + b
__global__ void __launch_bounds__(256) agg_kernel(
    const float* __restrict__ bias, float* __restrict__ out, int N)
{
    int w    = (int)((blockIdx.x * blockDim.x + threadIdx.x) >> 5);
    int lane = threadIdx.x & 31;
    if (w >= N) return;

    const float4* H4 = (const float4*)g_h;
    float4 acc = H4[(size_t)w * 32 + lane];   // self-loop term: h_s[i]
    int beg = g_off[w], end = g_off[w + 1];

    int e = beg;
    for (; e + 1 < end; e += 2) {
        int s0 = g_col[e], s1 = g_col[e + 1];
        float4 v0 = H4[(size_t)s0 * 32 + lane];
        float4 v1 = H4[(size_t)s1 * 32 + lane];
        acc.x += v0.x + v1.x; acc.y += v0.y + v1.y;
        acc.z += v0.z + v1.z; acc.w += v0.w + v1.w;
    }
    if (e < end) {
        int s0 = g_col[e];
        float4 v0 = H4[(size_t)s0 * 32 + lane];
        acc.x += v0.x; acc.y += v0.y; acc.z += v0.z; acc.w += v0.w;
    }

    float dv = g_dinv[w];
    float4 bb = ((const float4*)bias)[lane];
    float4 o;
    o.x = fmaf(acc.x, dv, bb.x);
    o.y = fmaf(acc.y, dv, bb.y);
    o.z = fmaf(acc.z, dv, bb.z);
    o.w = fmaf(acc.w, dv, bb.w);
    ((float4*)out)[(size_t)w * 32 + lane] = o;
}

__global__ void zero_row0_kernel(float* __restrict__ out) {
    int t = threadIdx.x;
    if (t < D) out[t] = 0.f;
}

// ---------------------------------------------------------------- launch
extern "C" void kernel_launch(void* const* d_in, const int* in_sizes, int n_in,
                              void* d_out, int out_size)
{
    const float* emb = (const float*)d_in[0];
    const float* W1  = (const float*)d_in[1];
    const float* b1  = (const float*)d_in[2];
    const float* W2  = (const float*)d_in[3];
    const float* b2  = (const float*)d_in[4];
    const float* W3  = (const float*)d_in[5];
    const float* b3  = (const float*)d_in[6];
    const void*  ei  = d_in[7];

    int N = in_sizes[0] / D;
    int E = in_sizes[7] / 2;
    float* out = (float*)d_out;

    void* p;
    cudaGetSymbolAddress(&p, g_h);  float* H = (float*)p;
    cudaGetSymbolAddress(&p, g_x);  float* X = (float*)p;

    static int smem_set = 0;
    if (!smem_set) {
        cudaFuncSetAttribute(gemm_tc_kernel,
            cudaFuncAttributeMaxDynamicSharedMemorySize, SM_TOT);
        smem_set = 1;
    }

    int tb = 256;
    detect_kernel<<<1, 1>>>((const int*)ei);
    zero_cnt_kernel<<<(N + tb - 1) / tb, tb>>>(N);
    count_kernel<<<(E + tb - 1) / tb, tb>>>(ei, E);
    dinv_kernel<<<(N + tb - 1) / tb, tb>>>(N);
    scan_kernel<<<1, 1024>>>(N);
    fill_kernel<<<(E + tb - 1) / tb, tb>>>(ei, E);

    int gemm_grid = (N + 63) / 64;
    int agg_grid  = (N + 7) / 8;
    int ws_grid   = (D * D + tb - 1) / tb;

    // layer 1
    wsplit_kernel<<<ws_grid, tb>>>(W1);
    gemm_tc_kernel<<<gemm_grid, 256, SM_TOT>>>(emb, H, N, 0);
    agg_kernel<<<agg_grid, 256>>>(b1, X, N);
    // layer 2 (relu fused into A-load)
    wsplit_kernel<<<ws_grid, tb>>>(W2);
    gemm_tc_kernel<<<gemm_grid, 256, SM_TOT>>>(X, H, N, 1);
    agg_kernel<<<agg_grid, 256>>>(b2, X, N);
    // layer 3
    wsplit_kernel<<<ws_grid, tb>>>(W3);
    gemm_tc_kernel<<<gemm_grid, 256, SM_TOT>>>(X, H, N, 1);
    agg_kernel<<<agg_grid, 256>>>(b3, out, N);

    zero_row0_kernel<<<1, 128>>>(out);
}